// round 5
// baseline (speedup 1.0000x reference)
#include <cuda_runtime.h>
#include <cstdint>

// Fixed shapes: x,y float32 (4,4096,6)
#define BB 4
#define NN 4096
#define NPTS (BB*NN)
#define NBLK 128                      // k_pre grid (co-resident for grid barrier)
#define LOG2E 1.4426950408889634f
#define LN2F  0.6931471805599453f
#define EPS2  1e-4f
#define BLOG  (-8.317766166719343f)   // -log(4096)
#define EBLOG (2.44140625e-4f)        // exp(BLOG)
#define POS_INF (__int_as_float(0x7f800000))
#define NEG_INF (__int_as_float(0xff800000))
#define PBUFF (8*NN*8)                // floats per P buffer (8 segs x 4096 j x 8 floats)

// ---- f32x2 packed-math helpers ----
#define FMA2(d,a,b,c) asm("fma.rn.f32x2 %0, %1, %2, %3;" : "=l"(d) : "l"(a), "l"(b), "l"(c))
__device__ __forceinline__ unsigned long long pack2(float lo, float hi) {
    unsigned long long d;
    asm("mov.b64 %0, {%1, %2};" : "=l"(d) : "r"(__float_as_uint(lo)), "r"(__float_as_uint(hi)));
    return d;
}
__device__ __forceinline__ void unpack2(float& lo, float& hi, unsigned long long d) {
    unsigned int a, b;
    asm("mov.b64 {%0, %1}, %2;" : "=r"(a), "=r"(b) : "l"(d));
    lo = __uint_as_float(a); hi = __uint_as_float(b);
}
__device__ __forceinline__ float ex2(float x) {
    float r; asm("ex2.approx.ftz.f32 %0, %1;" : "=f"(r) : "f"(x)); return r;
}
__device__ __forceinline__ float lg2(float x) {
    float r; asm("lg2.approx.ftz.f32 %0, %1;" : "=f"(r) : "f"(x)); return r;
}

// -------- device scratch --------
__device__ __align__(16) float d_U[NPTS*8];
__device__ __align__(16) float d_V[NPTS*8];
__device__ __align__(16) float d_Pbuf[2*PBUFF];   // split layout per seg: [A: j*4][B: j*4]
__device__ float d_f[2][NPTS];
__device__ float d_g[2][NPTS];
__device__ float d_M0[8*32];
__device__ float d_M1[8*32];
__device__ float d_red[NBLK][16];
__device__ unsigned d_gen[4];
__device__ unsigned d_cnt[4];

// -------- software grid barrier (NBLK blocks co-resident) --------
__device__ __forceinline__ void grid_barrier(int k) {
    __syncthreads();
    if (threadIdx.x == 0) {
        __threadfence();
        unsigned g = d_gen[k];
        unsigned t = atomicAdd(&d_cnt[k], 1);
        if (t == NBLK - 1) {
            d_cnt[k] = 0;
            __threadfence();
            atomicExch(&d_gen[k], g + 1);
        } else {
            while (*((volatile unsigned*)&d_gen[k]) == g) { }
        }
        __threadfence();
    }
    __syncthreads();
}

__device__ __forceinline__ void reduce28_atomic(const float* acc, float* gdst) {
    int lane = threadIdx.x & 31;
    float mine = 0.f;
    #pragma unroll
    for (int c = 0; c < 28; ++c) {
        float v = acc[c];
        #pragma unroll
        for (int o = 16; o; o >>= 1) v += __shfl_xor_sync(0xffffffffu, v, o);
        if (lane == c) mine = v;
    }
    if (lane < 28) atomicAdd(gdst + lane, mine);
}

__device__ __forceinline__ float eval_poly(const float* __restrict__ M, const float* u) {
    float m[28];
    #pragma unroll
    for (int c = 0; c < 28; ++c) m[c] = M[c];
    float S = m[0];
    int cnt = 7;
    #pragma unroll
    for (int k = 0; k < 6; ++k) {
        float inner = m[1+k];
        inner = fmaf(0.5f * m[cnt], u[k], inner);
        cnt++;
        #pragma unroll
        for (int l = k+1; l < 6; ++l) { inner = fmaf(m[cnt], u[l], inner); cnt++; }
        S = fmaf(u[k], inner, S);
    }
    return S;
}

// write one column j in split layout: segbase points at seg start (NN*8 floats)
__device__ __forceinline__ void write_pack_split(float* segbase, int j, const float* u,
                                                 float cw, float h2) {
    reinterpret_cast<float4*>(segbase)[j] = make_float4(u[0]*cw, u[1]*cw, u[2]*cw, u[3]*cw);
    reinterpret_cast<float4*>(segbase + (size_t)NN*4)[j] = make_float4(u[4]*cw, u[5]*cw, h2, 0.f);
}

// ============ k_pre: reduce -> build+moments0 -> poly0(+M1) -> poly1(+pack) ============
__global__ void __launch_bounds__(256) k_pre(const float* __restrict__ x,
                                             const float* __restrict__ y) {
    const int tid = threadIdx.x;
    const int p = blockIdx.x * 256 + tid;
    const int lane = tid & 31, warp = tid >> 5;
    const int q = (p < NPTS) ? p : p - NPTS;
    const bool isx = (p < NPTS);
    const int b = q >> 12;

    // ---------- Phase R: reduction of 13 stats ----------
    float rv[13];
    {
        const float* src = isx ? (x + (size_t)q*6) : (y + (size_t)q*6);
        float c[6];
        #pragma unroll
        for (int k = 0; k < 6; ++k) c[k] = src[k];
        rv[0] = c[0]*c[0] + c[1]*c[1] + c[2]*c[2];
        #pragma unroll
        for (int k = 0; k < 6; ++k) { rv[1+k] = c[k]; rv[7+k] = c[k]; }
    }
    #pragma unroll
    for (int o = 16; o; o >>= 1) {
        rv[0] = fmaxf(rv[0], __shfl_xor_sync(0xffffffffu, rv[0], o));
        #pragma unroll
        for (int k = 1; k <= 6; ++k) rv[k] = fminf(rv[k], __shfl_xor_sync(0xffffffffu, rv[k], o));
        #pragma unroll
        for (int k = 7; k <= 12; ++k) rv[k] = fmaxf(rv[k], __shfl_xor_sync(0xffffffffu, rv[k], o));
    }
    __shared__ float swr[8][13];
    if (lane == 0) {
        #pragma unroll
        for (int k = 0; k < 13; ++k) swr[warp][k] = rv[k];
    }
    if (blockIdx.x == 0) { d_M0[tid] = 0.f; d_M1[tid] = 0.f; }
    __syncthreads();
    if (tid == 0) {
        float a[13];
        #pragma unroll
        for (int k = 0; k < 13; ++k) a[k] = swr[0][k];
        for (int w = 1; w < 8; ++w) {
            a[0] = fmaxf(a[0], swr[w][0]);
            #pragma unroll
            for (int k = 1; k <= 6; ++k) a[k] = fminf(a[k], swr[w][k]);
            #pragma unroll
            for (int k = 7; k <= 12; ++k) a[k] = fmaxf(a[k], swr[w][k]);
        }
        #pragma unroll
        for (int k = 0; k < 13; ++k) d_red[blockIdx.x][k] = a[k];
    }
    grid_barrier(0);

    __shared__ float sg[128*13];
    if (tid < 128) {
        #pragma unroll
        for (int k = 0; k < 13; ++k) sg[tid*13 + k] = d_red[tid][k];
    }
    __syncthreads();
    for (int s = 64; s >= 1; s >>= 1) {
        if (tid < s) {
            sg[tid*13+0] = fmaxf(sg[tid*13+0], sg[(tid+s)*13+0]);
            #pragma unroll
            for (int k = 1; k <= 6; ++k) sg[tid*13+k] = fminf(sg[tid*13+k], sg[(tid+s)*13+k]);
            #pragma unroll
            for (int k = 7; k <= 12; ++k) sg[tid*13+k] = fmaxf(sg[tid*13+k], sg[(tid+s)*13+k]);
        }
        __syncthreads();
    }
    const float s_scale = 1.f / (sqrtf(sg[0]) + 1e-6f);
    float eps1;
    {
        float e = 0.f;
        #pragma unroll
        for (int k = 0; k < 6; ++k) { float d = sg[7+k] - sg[1+k]; e += d * d; }
        eps1 = e;
    }
    const float inv_e1 = 1.f / eps1;

    // ---------- Phase B: build U/V + stage-0 moments ----------
    float u[6], sq;
    {
        const float* src = isx ? (x + (size_t)q*6) : (y + (size_t)q*6);
        float* dst = isx ? (d_U + (size_t)q*8) : (d_V + (size_t)q*8);
        u[0] = src[0]*s_scale; u[1] = src[1]*s_scale; u[2] = src[2]*s_scale;
        u[3] = 0.1f * fminf(fmaxf(src[3], 0.f), 1.f);
        u[4] = 0.1f * fminf(fmaxf(src[4], 0.f), 1.f);
        u[5] = 0.1f * fminf(fmaxf(src[5], 0.f), 1.f);
        sq = u[0]*u[0]+u[1]*u[1]+u[2]*u[2]+u[3]*u[3]+u[4]*u[4]+u[5]*u[5];
        reinterpret_cast<float4*>(dst)[0] = make_float4(u[0], u[1], u[2], u[3]);
        reinterpret_cast<float4*>(dst)[1] = make_float4(u[4], u[5], sq, 0.f);
    }
    float w6[6];
    #pragma unroll
    for (int k = 0; k < 6; ++k) w6[k] = 2.f * u[k] * inv_e1;
    {
        int seg0 = (isx ? 4 : 0) + b;
        float om = ex2(LOG2E * ((0.f - sq) * inv_e1 + BLOG));
        float acc[28];
        acc[0] = om;
        #pragma unroll
        for (int k = 0; k < 6; ++k) acc[1+k] = om * w6[k];
        int cnt = 7;
        #pragma unroll
        for (int k = 0; k < 6; ++k)
            #pragma unroll
            for (int l = k; l < 6; ++l) acc[cnt++] = acc[1+k] * w6[l];
        reduce28_atomic(acc, d_M0 + seg0*32);
    }
    grid_barrier(1);

    // ---------- Phase P0 ----------
    const int dir = isx ? 0 : 1;
    {
        int rowseg = dir*4 + b;
        float S = eval_poly(d_M0 + rowseg*32, u);
        float val = sq - eps1 * logf(S);
        if (dir == 0) d_f[0][q] = val; else d_g[0][q] = val;
        float om = __fdividef(EBLOG, S);
        int colseg = (dir^1)*4 + b;
        float acc[28];
        acc[0] = om;
        #pragma unroll
        for (int k = 0; k < 6; ++k) acc[1+k] = om * w6[k];
        int cnt = 7;
        #pragma unroll
        for (int k = 0; k < 6; ++k)
            #pragma unroll
            for (int l = k; l < 6; ++l) acc[cnt++] = acc[1+k] * w6[l];
        reduce28_atomic(acc, d_M1 + colseg*32);
    }
    grid_barrier(2);

    // ---------- Phase P1: f1/g1 + pack eps2 columns -> Pbuf[0] ----------
    {
        int rowseg = dir*4 + b;
        float S = eval_poly(d_M1 + rowseg*32, u);
        float val = sq - eps1 * logf(S);
        float prev = (dir == 0) ? d_f[0][q] : d_g[0][q];
        float res = 0.5f * (prev + val);
        if (dir == 0) d_f[1][q] = res; else d_g[1][q] = res;

        int colseg = (dir^1)*4 + b;
        float cw = 2.f * LOG2E / EPS2;
        float h2 = LOG2E * BLOG + (res - sq) * (LOG2E / EPS2);
        write_pack_split(d_Pbuf + (size_t)colseg*NN*8, q & (NN-1), u, cw, h2);
    }
}

// ---- dot: 8 rows (4 f32x2 pairs) against one column ----
__device__ __forceinline__ void dot8(const unsigned long long U[4][6],
                                     float4 wa, float4 wb, float* a) {
    unsigned long long W0 = pack2(wa.x, wa.x), W1 = pack2(wa.y, wa.y);
    unsigned long long W2 = pack2(wa.z, wa.z), W3 = pack2(wa.w, wa.w);
    unsigned long long W4 = pack2(wb.x, wb.x), W5 = pack2(wb.y, wb.y);
    unsigned long long H  = pack2(wb.z, wb.z);
    #pragma unroll
    for (int p = 0; p < 4; ++p) {
        unsigned long long A;
        FMA2(A, U[p][0], W0, H);
        FMA2(A, U[p][1], W1, A);
        FMA2(A, U[p][2], W2, A);
        FMA2(A, U[p][3], W3, A);
        FMA2(A, U[p][4], W4, A);
        FMA2(A, U[p][5], W5, A);
        unpack2(a[2*p], a[2*p+1], A);
    }
}

// ============ eps2 main: lane-varying j, 8 rows/warp, full j-range per block ============
// grid = (64 rowtiles, 8 segs), block 256 (8 warps). Warp owns rows [tile*64+warp*8, +8).
template<bool HASNEXT>
__global__ void __launch_bounds__(256, 2) k_main(int srcpp, int dstpp, int cur,
                                                 float alpha, float beta) {
    const int seg = blockIdx.y;
    const int b = seg & 3;
    const int dir = seg >> 2;
    const float* Rows = (dir ? d_V : d_U) + (size_t)b*NN*8;
    const float* fin  = (dir ? d_g[cur] : d_f[cur]) + (size_t)b*NN;
    float* fout       = (dir ? d_g[cur^1] : d_f[cur^1]) + (size_t)b*NN;
    const float4* PA  = reinterpret_cast<const float4*>(d_Pbuf + (size_t)srcpp*PBUFF + (size_t)seg*NN*8);
    const float4* PB  = PA + NN;

    const int lane = threadIdx.x & 31;
    const int warp = threadIdx.x >> 5;
    const int rowbase = blockIdx.x * 64 + warp * 8;

    // 8 rows as 4 f32x2 pairs (uniform across lanes)
    unsigned long long U[4][6];
    #pragma unroll
    for (int p = 0; p < 4; ++p) {
        const float* r0 = Rows + (size_t)(rowbase + 2*p)*8;
        const float* r1 = Rows + (size_t)(rowbase + 2*p + 1)*8;
        #pragma unroll
        for (int k = 0; k < 6; ++k) U[p][k] = pack2(r0[k], r1[k]);
    }

    float m[8], s[8];
    #pragma unroll
    for (int r = 0; r < 8; ++r) { m[r] = NEG_INF; s[r] = 0.f; }

    #pragma unroll 1
    for (int it = 0; it < 64; ++it) {
        const int j1 = it*64 + lane;
        const int j2 = j1 + 32;
        float4 wa1 = PA[j1], wb1 = PB[j1];
        float4 wa2 = PA[j2], wb2 = PB[j2];
        float a1[8], a2[8];
        dot8(U, wa1, wb1, a1);
        dot8(U, wa2, wb2, a2);
        #pragma unroll
        for (int r = 0; r < 8; ++r) {
            float x1 = a1[r], x2 = a2[r];
            float hi = fmaxf(x1, x2);
            float c  = ex2(-fabsf(x1 - x2));
            float w  = 1.f + c;                    // pair weight at base hi
            float d  = hi - m[r];
            float e  = ex2(-fabsf(d));
            bool up  = d > 0.f;
            float t  = up ? s[r] : w;
            float o  = up ? w : s[r];
            s[r] = fmaf(t, e, o);
            m[r] = fmaxf(m[r], hi);
        }
    }

    // cross-lane (m,s) logsumexp butterfly — all lanes end with merged values
    #pragma unroll
    for (int o = 16; o; o >>= 1) {
        #pragma unroll
        for (int r = 0; r < 8; ++r) {
            float mo = __shfl_xor_sync(0xffffffffu, m[r], o);
            float so = __shfl_xor_sync(0xffffffffu, s[r], o);
            float M = fmaxf(m[r], mo);
            s[r] = s[r] * ex2(m[r] - M) + so * ex2(mo - M);
            m[r] = M;
        }
    }

    if (lane == 0) {
        const float cw = 2.f * LOG2E / EPS2;
        float* segdst = d_Pbuf + (size_t)dstpp*PBUFF + (size_t)((dir^1)*4 + b)*NN*8;
        #pragma unroll
        for (int r = 0; r < 8; ++r) {
            const int row = rowbase + r;
            const float* src = Rows + (size_t)row*8;
            float sq = src[6];
            float val = sq - EPS2 * LN2F * (m[r] + lg2(s[r]));
            float res = beta * val;
            if (alpha != 0.f) res = fmaf(alpha, fin[row], res);
            fout[row] = res;
            if (HASNEXT) {
                float u[6];
                u[0]=src[0]; u[1]=src[1]; u[2]=src[2]; u[3]=src[3]; u[4]=src[4]; u[5]=src[5];
                float h2 = LOG2E * BLOG + (res - sq) * (LOG2E / EPS2);
                write_pack_split(segdst, row, u, cw, h2);
            }
        }
    }
}

// ============ final mean ============
__global__ void k_out(float* __restrict__ out) {
    float sum = 0.f;
    for (int i = threadIdx.x; i < NPTS; i += 256)
        sum += d_f[1][i] + d_g[1][i];
    #pragma unroll
    for (int o = 16; o; o >>= 1) sum += __shfl_xor_sync(0xffffffffu, sum, o);
    __shared__ float sw[8];
    int lane = threadIdx.x & 31, w = threadIdx.x >> 5;
    if (lane == 0) sw[w] = sum;
    __syncthreads();
    if (threadIdx.x == 0) {
        float t = 0.f;
        #pragma unroll
        for (int wi = 0; wi < 8; ++wi) t += sw[wi];
        out[0] = t * (10.f / (float)NPTS);
    }
}

extern "C" void kernel_launch(void* const* d_in, const int* in_sizes, int n_in,
                              void* d_out, int out_size) {
    (void)in_sizes; (void)n_in; (void)out_size;
    const float* x = (const float*)d_in[0];
    const float* y = (const float*)d_in[1];
    float* out = (float*)d_out;

    dim3 gm(64, 8);
    k_pre<<<NBLK, 256>>>(x, y);                            // f1/g1 + Pbuf[0]
    // stage 2: f2 = 0.5*(f1 + softmin), pack Pbuf[1]
    k_main<true ><<<gm, 256>>>(0, 1, 1, 0.5f, 0.5f);
    // stage 3: f_new = softmin only
    k_main<false><<<gm, 256>>>(1, 0, 0, 0.0f, 1.0f);
    k_out<<<1, 256>>>(out);
}